// round 1
// baseline (speedup 1.0000x reference)
#include <cuda_runtime.h>

#define TPB   256
#define NWARP 8
#define RB    8
#define NBLK  296

// Scratch (device globals: allocation-free rule)
__device__ float g_h  [50000 * 128];
__device__ float g_A  [50000 * 128];
__device__ float g_B  [50000 * 128];
__device__ float g_agg[50000 * 128];
__device__ float g_pool[64 * 128];
__device__ float g_cnt [64];

__device__ __forceinline__ float4 relu4(float4 v) {
    v.x = fmaxf(v.x, 0.f); v.y = fmaxf(v.y, 0.f);
    v.z = fmaxf(v.z, 0.f); v.w = fmaxf(v.w, 0.f);
    return v;
}

// ---------------------------------------------------------------------------
// Y[r, 0:128] = (RELU_IN ? relu(X[r]) : X[r]) @ W[128,128] + bias
// Warp processes RB rows per task; W staged in smem; per-warp row buffer.
// ---------------------------------------------------------------------------
template <bool RELU_IN>
__global__ void __launch_bounds__(TPB)
gemm128_kernel(const float* __restrict__ X, const float* __restrict__ W,
               const float* __restrict__ bias, float* __restrict__ Y, int nrows)
{
    extern __shared__ float sm[];
    float* Ws = sm;                 // 128*128
    float* xb = sm + 128 * 128;     // NWARP*RB*128

    for (int i = threadIdx.x; i < 128 * 128 / 4; i += TPB)
        ((float4*)Ws)[i] = ((const float4*)W)[i];
    __syncthreads();

    const int warp = threadIdx.x >> 5, lane = threadIdx.x & 31;
    float* tb = xb + warp * RB * 128;

    float4 bv = make_float4(0.f, 0.f, 0.f, 0.f);
    if (bias) bv = ((const float4*)bias)[lane];

    const int gwarp  = blockIdx.x * NWARP + warp;
    const int nwarps = gridDim.x * NWARP;
    const int ntasks = (nrows + RB - 1) / RB;

    for (int task = gwarp; task < ntasks; task += nwarps) {
        const int row0 = task * RB;
        #pragma unroll
        for (int e = 0; e < RB; e++) {
            int r = row0 + e;
            float4 v = make_float4(0.f, 0.f, 0.f, 0.f);
            if (r < nrows) v = ((const float4*)(X + (size_t)r * 128))[lane];
            if (RELU_IN) v = relu4(v);
            ((float4*)(tb + e * 128))[lane] = v;
        }
        __syncwarp();

        float4 acc[RB];
        #pragma unroll
        for (int e = 0; e < RB; e++) acc[e] = make_float4(0.f, 0.f, 0.f, 0.f);

        #pragma unroll 2
        for (int kb = 0; kb < 32; kb++) {
            float4 w0 = ((const float4*)(Ws + (kb * 4 + 0) * 128))[lane];
            float4 w1 = ((const float4*)(Ws + (kb * 4 + 1) * 128))[lane];
            float4 w2 = ((const float4*)(Ws + (kb * 4 + 2) * 128))[lane];
            float4 w3 = ((const float4*)(Ws + (kb * 4 + 3) * 128))[lane];
            #pragma unroll
            for (int e = 0; e < RB; e++) {
                float4 xv = ((const float4*)(tb + e * 128))[kb];
                acc[e].x += xv.x * w0.x + xv.y * w1.x + xv.z * w2.x + xv.w * w3.x;
                acc[e].y += xv.x * w0.y + xv.y * w1.y + xv.z * w2.y + xv.w * w3.y;
                acc[e].z += xv.x * w0.z + xv.y * w1.z + xv.z * w2.z + xv.w * w3.z;
                acc[e].w += xv.x * w0.w + xv.y * w1.w + xv.z * w2.w + xv.w * w3.w;
            }
        }

        #pragma unroll
        for (int e = 0; e < RB; e++) {
            int r = row0 + e;
            if (r < nrows) {
                float4 o = acc[e];
                o.x += bv.x; o.y += bv.y; o.z += bv.z; o.w += bv.w;
                ((float4*)(Y + (size_t)r * 128))[lane] = o;
            }
        }
        __syncwarp();
    }
}

// ---------------------------------------------------------------------------
// For edge e (incl. self loops at idx >= Ereal):
//   t = relu(A[dst] + B[src]);  msg = t @ W2 + b2;  agg[dst] += msg (atomic)
// ---------------------------------------------------------------------------
__global__ void __launch_bounds__(TPB)
edge_kernel(const float* __restrict__ A, const float* __restrict__ Bm,
            const int* __restrict__ src, const int* __restrict__ dst,
            const float* __restrict__ W2, const float* __restrict__ b2,
            float* __restrict__ agg, int Ereal, int Etot)
{
    extern __shared__ float sm[];
    float* Ws = sm;
    float* xb = sm + 128 * 128;

    for (int i = threadIdx.x; i < 128 * 128 / 4; i += TPB)
        ((float4*)Ws)[i] = ((const float4*)W2)[i];
    __syncthreads();

    const int warp = threadIdx.x >> 5, lane = threadIdx.x & 31;
    float* tb = xb + warp * RB * 128;

    const float4 bv = ((const float4*)b2)[lane];

    const int gwarp  = blockIdx.x * NWARP + warp;
    const int nwarps = gridDim.x * NWARP;
    const int ntasks = (Etot + RB - 1) / RB;

    for (int task = gwarp; task < ntasks; task += nwarps) {
        const int e0 = task * RB;
        int dd[RB];
        #pragma unroll
        for (int e = 0; e < RB; e++) {
            int idx = e0 + e;
            bool valid = idx < Etot;
            int s = 0, d = 0;
            if (valid) {
                if (idx < Ereal) { s = src[idx]; d = dst[idx]; }
                else             { s = d = idx - Ereal; }
            }
            dd[e] = valid ? d : -1;
            float4 a = ((const float4*)(A  + (size_t)d * 128))[lane];
            float4 b = ((const float4*)(Bm + (size_t)s * 128))[lane];
            float4 t = make_float4(a.x + b.x, a.y + b.y, a.z + b.z, a.w + b.w);
            ((float4*)(tb + e * 128))[lane] = relu4(t);
        }
        __syncwarp();

        float4 acc[RB];
        #pragma unroll
        for (int e = 0; e < RB; e++) acc[e] = make_float4(0.f, 0.f, 0.f, 0.f);

        #pragma unroll 2
        for (int kb = 0; kb < 32; kb++) {
            float4 w0 = ((const float4*)(Ws + (kb * 4 + 0) * 128))[lane];
            float4 w1 = ((const float4*)(Ws + (kb * 4 + 1) * 128))[lane];
            float4 w2 = ((const float4*)(Ws + (kb * 4 + 2) * 128))[lane];
            float4 w3 = ((const float4*)(Ws + (kb * 4 + 3) * 128))[lane];
            #pragma unroll
            for (int e = 0; e < RB; e++) {
                float4 xv = ((const float4*)(tb + e * 128))[kb];
                acc[e].x += xv.x * w0.x + xv.y * w1.x + xv.z * w2.x + xv.w * w3.x;
                acc[e].y += xv.x * w0.y + xv.y * w1.y + xv.z * w2.y + xv.w * w3.y;
                acc[e].z += xv.x * w0.z + xv.y * w1.z + xv.z * w2.z + xv.w * w3.z;
                acc[e].w += xv.x * w0.w + xv.y * w1.w + xv.z * w2.w + xv.w * w3.w;
            }
        }

        #pragma unroll
        for (int e = 0; e < RB; e++) {
            if (dd[e] >= 0) {
                float* p = agg + (size_t)dd[e] * 128 + lane * 4;
                atomicAdd(p + 0, acc[e].x + bv.x);
                atomicAdd(p + 1, acc[e].y + bv.y);
                atomicAdd(p + 2, acc[e].z + bv.z);
                atomicAdd(p + 3, acc[e].w + bv.w);
            }
        }
        __syncwarp();
    }
}

// ---------------------------------------------------------------------------
// Pool: per node, pool[batch[n]] += relu(agg[n]); cnt[batch[n]] += 1
// ---------------------------------------------------------------------------
__global__ void pool_kernel(const float* __restrict__ agg, const int* __restrict__ batch,
                            float* __restrict__ pool, float* __restrict__ cnt, int n)
{
    int gw   = (blockIdx.x * blockDim.x + threadIdx.x) >> 5;
    int lane = threadIdx.x & 31;
    int nw   = (gridDim.x * blockDim.x) >> 5;
    for (int node = gw; node < n; node += nw) {
        int g = batch[node];
        float4 v = relu4(((const float4*)(agg + (size_t)node * 128))[lane]);
        float* p = pool + (size_t)g * 128 + lane * 4;
        atomicAdd(p + 0, v.x); atomicAdd(p + 1, v.y);
        atomicAdd(p + 2, v.z); atomicAdd(p + 3, v.w);
        if (lane == 0) atomicAdd(&cnt[g], 1.f);
    }
}

// out[g, o] = (pool[g]/max(cnt,1)) @ W[128,64] + b[64]
__global__ void final_kernel(const float* __restrict__ pool, const float* __restrict__ cnt,
                             const float* __restrict__ W, const float* __restrict__ b,
                             float* __restrict__ out)
{
    __shared__ float p[128];
    int g = blockIdx.x;
    float c = fmaxf(cnt[g], 1.f);
    for (int j = threadIdx.x; j < 128; j += blockDim.x)
        p[j] = pool[(size_t)g * 128 + j] / c;
    __syncthreads();
    int o = threadIdx.x;
    float s = b[o];
    #pragma unroll 4
    for (int j = 0; j < 128; j++) s += p[j] * W[j * 64 + o];
    out[(size_t)g * 64 + o] = s;
}

extern "C" void kernel_launch(void* const* d_in, const int* in_sizes, int n_in,
                              void* d_out, int out_size)
{
    const float* x     = (const float*)d_in[0];
    const int*   ei    = (const int*)  d_in[1];
    const int*   batch = (const int*)  d_in[3];
    const int N = in_sizes[0] / 128;
    const int E = in_sizes[1] / 2;
    const int* src = ei;
    const int* dst = ei + E;

    const float* lin_w[3] = { (const float*)d_in[4],  (const float*)d_in[10], (const float*)d_in[16] };
    const float* lin_b[3] = { (const float*)d_in[5],  (const float*)d_in[11], (const float*)d_in[17] };
    const float* w1[3]    = { (const float*)d_in[6],  (const float*)d_in[12], (const float*)d_in[18] };
    const float* b1[3]    = { (const float*)d_in[7],  (const float*)d_in[13], (const float*)d_in[19] };
    const float* w2[3]    = { (const float*)d_in[8],  (const float*)d_in[14], (const float*)d_in[20] };
    const float* b2[3]    = { (const float*)d_in[9],  (const float*)d_in[15], (const float*)d_in[21] };
    const float* out_w    = (const float*)d_in[22];
    const float* out_b    = (const float*)d_in[23];
    float* out = (float*)d_out;

    float *h_, *A_, *B_, *agg_, *pool_, *cnt_;
    cudaGetSymbolAddress((void**)&h_,    g_h);
    cudaGetSymbolAddress((void**)&A_,    g_A);
    cudaGetSymbolAddress((void**)&B_,    g_B);
    cudaGetSymbolAddress((void**)&agg_,  g_agg);
    cudaGetSymbolAddress((void**)&pool_, g_pool);
    cudaGetSymbolAddress((void**)&cnt_,  g_cnt);

    const int smemBytes = (128 * 128 + NWARP * RB * 128) * sizeof(float); // 96 KB
    cudaFuncSetAttribute((const void*)gemm128_kernel<false>,
                         cudaFuncAttributeMaxDynamicSharedMemorySize, smemBytes);
    cudaFuncSetAttribute((const void*)gemm128_kernel<true>,
                         cudaFuncAttributeMaxDynamicSharedMemorySize, smemBytes);
    cudaFuncSetAttribute((const void*)edge_kernel,
                         cudaFuncAttributeMaxDynamicSharedMemorySize, smemBytes);

    const int Etot = E + N;
    const int G = out_size / 64;

    for (int l = 0; l < 3; l++) {
        const float* X = (l == 0) ? x : agg_;
        if (l == 0)
            gemm128_kernel<false><<<NBLK, TPB, smemBytes>>>(X, lin_w[l], lin_b[l], h_, N);
        else
            gemm128_kernel<true ><<<NBLK, TPB, smemBytes>>>(X, lin_w[l], lin_b[l], h_, N);
        // A = h @ w1[0:128,:] + b1   (multiplies h[dst])
        gemm128_kernel<false><<<NBLK, TPB, smemBytes>>>(h_, w1[l],              b1[l],  A_, N);
        // B = h @ w1[128:256,:]      (multiplies h[src])
        gemm128_kernel<false><<<NBLK, TPB, smemBytes>>>(h_, w1[l] + 128 * 128, nullptr, B_, N);
        cudaMemsetAsync(agg_, 0, (size_t)N * 128 * sizeof(float));
        edge_kernel<<<NBLK, TPB, smemBytes>>>(A_, B_, src, dst, w2[l], b2[l], agg_, E, Etot);
    }

    cudaMemsetAsync(pool_, 0, (size_t)G * 128 * sizeof(float));
    cudaMemsetAsync(cnt_,  0, (size_t)G * sizeof(float));
    pool_kernel<<<256, 256>>>(agg_, batch, pool_, cnt_, N);
    final_kernel<<<G, 64>>>(pool_, cnt_, out_w, out_b, out);
}

// round 2
// speedup vs baseline: 1.1377x; 1.1377x over previous
#include <cuda_runtime.h>

#define TPB   256
#define NWARP 8
#define RB    8
#define NBLK  296

// Scratch (device globals: allocation-free rule)
__device__ float g_h  [50000 * 128];
__device__ float g_A  [50000 * 128];
__device__ float g_B  [50000 * 128];
__device__ float g_agg[50000 * 128];
__device__ float g_pool[64 * 128];
__device__ float g_cnt [64];

typedef unsigned long long u64;

__device__ __forceinline__ void ffma2(u64 &acc, u64 a, u64 b) {
    asm("fma.rn.f32x2 %0, %1, %2, %0;" : "+l"(acc) : "l"(a), "l"(b));
}
__device__ __forceinline__ float pairsum(u64 p) {
    float lo, hi;
    asm("mov.b64 {%0, %1}, %2;" : "=f"(lo), "=f"(hi) : "l"(p));
    return lo + hi;
}
__device__ __forceinline__ u64 packf2(float lo, float hi) {
    u64 r;
    asm("mov.b64 %0, {%1, %2};" : "=l"(r) : "f"(lo), "f"(hi));
    return r;
}

__device__ __forceinline__ float4 relu4(float4 v) {
    v.x = fmaxf(v.x, 0.f); v.y = fmaxf(v.y, 0.f);
    v.z = fmaxf(v.z, 0.f); v.w = fmaxf(v.w, 0.f);
    return v;
}

// Stage W[128,128] into k-pair layout: Wp[m*128+n] = (W[2m][n], W[2m+1][n])
__device__ __forceinline__ void stage_w_pairs(u64* Wp, const float* __restrict__ W) {
    for (int idx = threadIdx.x; idx < 64 * 128; idx += TPB) {
        int m = idx >> 7, n = idx & 127;
        Wp[idx] = packf2(W[(2 * m) * 128 + n], W[(2 * m + 1) * 128 + n]);
    }
}

// Inner product tile: acc[e][0..3] over columns {2L, 2L+1, 2L+64, 2L+65}
// tb: RB rows x 128 floats (row tile), Wp: pair-layout weights.
__device__ __forceinline__ void mm_tile(u64 acc[RB][4], const float* tb, const u64* Wp, int lane) {
    #pragma unroll 2
    for (int mm = 0; mm < 32; mm++) {
        const u64* r0 = Wp + (2 * mm) * 128;
        const u64* r1 = Wp + (2 * mm + 1) * 128;
        ulonglong2 wa0 = ((const ulonglong2*)r0)[lane];
        ulonglong2 wb0 = ((const ulonglong2*)r0)[lane + 32];
        ulonglong2 wa1 = ((const ulonglong2*)r1)[lane];
        ulonglong2 wb1 = ((const ulonglong2*)r1)[lane + 32];
        #pragma unroll
        for (int e = 0; e < RB; e++) {
            ulonglong2 xp = ((const ulonglong2*)(tb + e * 128))[mm];
            ffma2(acc[e][0], xp.x, wa0.x);
            ffma2(acc[e][1], xp.x, wa0.y);
            ffma2(acc[e][2], xp.x, wb0.x);
            ffma2(acc[e][3], xp.x, wb0.y);
            ffma2(acc[e][0], xp.y, wa1.x);
            ffma2(acc[e][1], xp.y, wa1.y);
            ffma2(acc[e][2], xp.y, wb1.x);
            ffma2(acc[e][3], xp.y, wb1.y);
        }
    }
}

// ---------------------------------------------------------------------------
// Y[r] = (RELU_IN ? relu(X[r]) : X[r]) @ W[128,128] + bias
// ---------------------------------------------------------------------------
template <bool RELU_IN>
__global__ void __launch_bounds__(TPB, 2)
gemm128_kernel(const float* __restrict__ X, const float* __restrict__ W,
               const float* __restrict__ bias, float* __restrict__ Y, int nrows)
{
    extern __shared__ float sm[];
    u64*   Wp = (u64*)sm;                      // 64*128 u64 = 64KB
    float* xb = sm + 64 * 128 * 2;             // NWARP*RB*128 floats = 32KB

    stage_w_pairs(Wp, W);
    __syncthreads();

    const int warp = threadIdx.x >> 5, lane = threadIdx.x & 31;
    float* tb = xb + warp * RB * 128;

    float2 b01 = make_float2(0.f, 0.f), b23 = make_float2(0.f, 0.f);
    if (bias) {
        b01 = ((const float2*)bias)[lane];
        b23 = ((const float2*)bias)[lane + 32];
    }

    const int gwarp  = blockIdx.x * NWARP + warp;
    const int nwarps = gridDim.x * NWARP;
    const int ntasks = (nrows + RB - 1) / RB;

    for (int task = gwarp; task < ntasks; task += nwarps) {
        const int row0 = task * RB;
        #pragma unroll
        for (int e = 0; e < RB; e++) {
            int r = row0 + e;
            float4 v = make_float4(0.f, 0.f, 0.f, 0.f);
            if (r < nrows) v = ((const float4*)(X + (size_t)r * 128))[lane];
            if (RELU_IN) v = relu4(v);
            ((float4*)(tb + e * 128))[lane] = v;
        }
        __syncwarp();

        u64 acc[RB][4];
        #pragma unroll
        for (int e = 0; e < RB; e++)
            acc[e][0] = acc[e][1] = acc[e][2] = acc[e][3] = 0ull;

        mm_tile(acc, tb, Wp, lane);

        #pragma unroll
        for (int e = 0; e < RB; e++) {
            int r = row0 + e;
            if (r < nrows) {
                float2 o01 = make_float2(pairsum(acc[e][0]) + b01.x,
                                         pairsum(acc[e][1]) + b01.y);
                float2 o23 = make_float2(pairsum(acc[e][2]) + b23.x,
                                         pairsum(acc[e][3]) + b23.y);
                ((float2*)(Y + (size_t)r * 128))[lane]      = o01;
                ((float2*)(Y + (size_t)r * 128))[lane + 32] = o23;
            }
        }
        __syncwarp();
    }
}

// ---------------------------------------------------------------------------
// edge e (self loops at idx >= Ereal):
//   t = relu(A[dst] + B[src]);  msg = t @ W2 + b2;  agg[dst] += msg (atomic)
// ---------------------------------------------------------------------------
__global__ void __launch_bounds__(TPB, 2)
edge_kernel(const float* __restrict__ A, const float* __restrict__ Bm,
            const int* __restrict__ src, const int* __restrict__ dst,
            const float* __restrict__ W2, const float* __restrict__ b2,
            float* __restrict__ agg, int Ereal, int Etot)
{
    extern __shared__ float sm[];
    u64*   Wp = (u64*)sm;
    float* xb = sm + 64 * 128 * 2;

    stage_w_pairs(Wp, W2);
    __syncthreads();

    const int warp = threadIdx.x >> 5, lane = threadIdx.x & 31;
    float* tb = xb + warp * RB * 128;

    const float2 b01 = ((const float2*)b2)[lane];
    const float2 b23 = ((const float2*)b2)[lane + 32];

    const int gwarp  = blockIdx.x * NWARP + warp;
    const int nwarps = gridDim.x * NWARP;
    const int ntasks = (Etot + RB - 1) / RB;

    for (int task = gwarp; task < ntasks; task += nwarps) {
        const int e0 = task * RB;
        int dd[RB];
        #pragma unroll
        for (int e = 0; e < RB; e++) {
            int idx = e0 + e;
            bool valid = idx < Etot;
            int s = 0, d = 0;
            if (valid) {
                if (idx < Ereal) { s = src[idx]; d = dst[idx]; }
                else             { s = d = idx - Ereal; }
            }
            dd[e] = valid ? d : -1;
            float4 a = ((const float4*)(A  + (size_t)d * 128))[lane];
            float4 b = ((const float4*)(Bm + (size_t)s * 128))[lane];
            float4 t = make_float4(a.x + b.x, a.y + b.y, a.z + b.z, a.w + b.w);
            ((float4*)(tb + e * 128))[lane] = relu4(t);
        }
        __syncwarp();

        u64 acc[RB][4];
        #pragma unroll
        for (int e = 0; e < RB; e++)
            acc[e][0] = acc[e][1] = acc[e][2] = acc[e][3] = 0ull;

        mm_tile(acc, tb, Wp, lane);

        #pragma unroll
        for (int e = 0; e < RB; e++) {
            if (dd[e] >= 0) {
                float* p = agg + (size_t)dd[e] * 128;
                atomicAdd(p + 2 * lane + 0,  pairsum(acc[e][0]) + b01.x);
                atomicAdd(p + 2 * lane + 1,  pairsum(acc[e][1]) + b01.y);
                atomicAdd(p + 2 * lane + 64, pairsum(acc[e][2]) + b23.x);
                atomicAdd(p + 2 * lane + 65, pairsum(acc[e][3]) + b23.y);
            }
        }
        __syncwarp();
    }
}

// ---------------------------------------------------------------------------
__global__ void pool_kernel(const float* __restrict__ agg, const int* __restrict__ batch,
                            float* __restrict__ pool, float* __restrict__ cnt, int n)
{
    int gw   = (blockIdx.x * blockDim.x + threadIdx.x) >> 5;
    int lane = threadIdx.x & 31;
    int nw   = (gridDim.x * blockDim.x) >> 5;
    for (int node = gw; node < n; node += nw) {
        int g = batch[node];
        float4 v = relu4(((const float4*)(agg + (size_t)node * 128))[lane]);
        float* p = pool + (size_t)g * 128 + lane * 4;
        atomicAdd(p + 0, v.x); atomicAdd(p + 1, v.y);
        atomicAdd(p + 2, v.z); atomicAdd(p + 3, v.w);
        if (lane == 0) atomicAdd(&cnt[g], 1.f);
    }
}

__global__ void final_kernel(const float* __restrict__ pool, const float* __restrict__ cnt,
                             const float* __restrict__ W, const float* __restrict__ b,
                             float* __restrict__ out)
{
    __shared__ float p[128];
    int g = blockIdx.x;
    float c = fmaxf(cnt[g], 1.f);
    for (int j = threadIdx.x; j < 128; j += blockDim.x)
        p[j] = pool[(size_t)g * 128 + j] / c;
    __syncthreads();
    int o = threadIdx.x;
    float s = b[o];
    #pragma unroll 4
    for (int j = 0; j < 128; j++) s += p[j] * W[j * 64 + o];
    out[(size_t)g * 64 + o] = s;
}

extern "C" void kernel_launch(void* const* d_in, const int* in_sizes, int n_in,
                              void* d_out, int out_size)
{
    const float* x     = (const float*)d_in[0];
    const int*   ei    = (const int*)  d_in[1];
    const int*   batch = (const int*)  d_in[3];
    const int N = in_sizes[0] / 128;
    const int E = in_sizes[1] / 2;
    const int* src = ei;
    const int* dst = ei + E;

    const float* lin_w[3] = { (const float*)d_in[4],  (const float*)d_in[10], (const float*)d_in[16] };
    const float* lin_b[3] = { (const float*)d_in[5],  (const float*)d_in[11], (const float*)d_in[17] };
    const float* w1[3]    = { (const float*)d_in[6],  (const float*)d_in[12], (const float*)d_in[18] };
    const float* b1[3]    = { (const float*)d_in[7],  (const float*)d_in[13], (const float*)d_in[19] };
    const float* w2[3]    = { (const float*)d_in[8],  (const float*)d_in[14], (const float*)d_in[20] };
    const float* b2[3]    = { (const float*)d_in[9],  (const float*)d_in[15], (const float*)d_in[21] };
    const float* out_w    = (const float*)d_in[22];
    const float* out_b    = (const float*)d_in[23];
    float* out = (float*)d_out;

    float *h_, *A_, *B_, *agg_, *pool_, *cnt_;
    cudaGetSymbolAddress((void**)&h_,    g_h);
    cudaGetSymbolAddress((void**)&A_,    g_A);
    cudaGetSymbolAddress((void**)&B_,    g_B);
    cudaGetSymbolAddress((void**)&agg_,  g_agg);
    cudaGetSymbolAddress((void**)&pool_, g_pool);
    cudaGetSymbolAddress((void**)&cnt_,  g_cnt);

    const int smemBytes = (64 * 128 * 2 + NWARP * RB * 128) * sizeof(float); // 96 KB
    cudaFuncSetAttribute((const void*)gemm128_kernel<false>,
                         cudaFuncAttributeMaxDynamicSharedMemorySize, smemBytes);
    cudaFuncSetAttribute((const void*)gemm128_kernel<true>,
                         cudaFuncAttributeMaxDynamicSharedMemorySize, smemBytes);
    cudaFuncSetAttribute((const void*)edge_kernel,
                         cudaFuncAttributeMaxDynamicSharedMemorySize, smemBytes);

    const int Etot = E + N;
    const int G = out_size / 64;

    for (int l = 0; l < 3; l++) {
        const float* X = (l == 0) ? x : agg_;
        if (l == 0)
            gemm128_kernel<false><<<NBLK, TPB, smemBytes>>>(X, lin_w[l], lin_b[l], h_, N);
        else
            gemm128_kernel<true ><<<NBLK, TPB, smemBytes>>>(X, lin_w[l], lin_b[l], h_, N);
        gemm128_kernel<false><<<NBLK, TPB, smemBytes>>>(h_, w1[l],             b1[l],  A_, N);
        gemm128_kernel<false><<<NBLK, TPB, smemBytes>>>(h_, w1[l] + 128 * 128, nullptr, B_, N);
        cudaMemsetAsync(agg_, 0, (size_t)N * 128 * sizeof(float));
        edge_kernel<<<NBLK, TPB, smemBytes>>>(A_, B_, src, dst, w2[l], b2[l], agg_, E, Etot);
    }

    cudaMemsetAsync(pool_, 0, (size_t)G * 128 * sizeof(float));
    cudaMemsetAsync(cnt_,  0, (size_t)G * sizeof(float));
    pool_kernel<<<256, 256>>>(agg_, batch, pool_, cnt_, N);
    final_kernel<<<G, 64>>>(pool_, cnt_, out_w, out_b, out);
}